// round 12
// baseline (speedup 1.0000x reference)
#include <cuda_runtime.h>
#include <cuda_fp16.h>
#include <math.h>
#include <stdint.h>

// Problem constants (B=4, T=2048, C=1024)
#define BATCH 4
#define SEQ   2048
#define CDIM  1024
#define MROWS (BATCH*SEQ)   // 8192

typedef __half fp16;

// ------------------------- scratch (__device__ globals) ---------------------
__device__ float g_S [(size_t)BATCH*SEQ*SEQ];
__device__ fp16 g_X [MROWS*CDIM];                        // A: single fp16
__device__ fp16 g_Q [MROWS*CDIM];                        // A: single fp16
__device__ fp16 g_Khi[MROWS*CDIM], g_Klo[MROWS*CDIM];    // B: hi/lo
__device__ fp16 g_VThi[MROWS*CDIM], g_VTlo[MROWS*CDIM];  // B: hi/lo, [C,T]/batch
__device__ fp16 g_P [(size_t)BATCH*SEQ*SEQ];             // A: single fp16
__device__ fp16 g_O1[MROWS*CDIM];                        // A: single fp16
__device__ fp16 g_WqThi[CDIM*CDIM], g_WqTlo[CDIM*CDIM];
__device__ fp16 g_WkThi[CDIM*CDIM], g_WkTlo[CDIM*CDIM];
__device__ fp16 g_WvThi[CDIM*CDIM], g_WvTlo[CDIM*CDIM];
__device__ fp16 g_WoThi[CDIM*CDIM], g_WoTlo[CDIM*CDIM];

// ------------------------- PTX helpers (sm_100 base target) -----------------
__device__ __forceinline__ uint32_t smem_u32(const void* p) {
    uint32_t a;
    asm("{ .reg .u64 t; cvta.to.shared.u64 t, %1; cvt.u32.u64 %0, t; }"
        : "=r"(a) : "l"(p));
    return a;
}
__device__ __forceinline__ void cp16(uint32_t s, const void* g) {
    asm volatile("cp.async.cg.shared.global [%0], [%1], 16;"
                 :: "r"(s), "l"(g) : "memory");
}
__device__ __forceinline__ void cp_commit() {
    asm volatile("cp.async.commit_group;" ::: "memory");
}
__device__ __forceinline__ void cp_wait0() {
    asm volatile("cp.async.wait_group 0;" ::: "memory");
}
__device__ __forceinline__ void cp_wait1() {
    asm volatile("cp.async.wait_group 1;" ::: "memory");
}
#define LDSM_X4(r0, r1, r2, r3, a) \
    asm volatile("ldmatrix.sync.aligned.m8n8.x4.shared.b16 {%0,%1,%2,%3}, [%4];" \
                 : "=r"(r0), "=r"(r1), "=r"(r2), "=r"(r3) : "r"(a))
#define MMA16816(c, a, b) \
    asm volatile("mma.sync.aligned.m16n8k16.row.col.f32.f16.f16.f32 " \
                 "{%0,%1,%2,%3}, {%4,%5,%6,%7}, {%8,%9}, {%0,%1,%2,%3};" \
                 : "+f"((c)[0]), "+f"((c)[1]), "+f"((c)[2]), "+f"((c)[3]) \
                 : "r"((a)[0]), "r"((a)[1]), "r"((a)[2]), "r"((a)[3]), \
                   "r"((b)[0]), "r"((b)[1]))

// SMEM tile geometry: 128 rows x 32 fp16, padded to 40 fp16 (80 B) per row.
// Stage = A + Bh + Bl (3 tiles).
#define ROWB 80
#define TILEB (128 * ROWB)           // 10240 B per tile
#define OFF_BH TILEB
#define OFF_BL (2 * TILEB)
#define STAGEB (3 * TILEB)           // 30720 B
#define NSTAGE 3
#define GEMM_SMEM (NSTAGE * STAGEB)  // 92160 B -> 2 CTAs/SM; also >= 128x132 f32

// ---------------------------------------------------------------------------
// Conversion kernels
// ---------------------------------------------------------------------------
__global__ void to_half(const float* __restrict__ in, fp16* __restrict__ out,
                        size_t n4) {
    size_t i = blockIdx.x * (size_t)blockDim.x + threadIdx.x;
    size_t stride = (size_t)gridDim.x * blockDim.x;
    const float4* in4 = (const float4*)in;
    __half2* o2 = (__half2*)out;
    for (; i < n4; i += stride) {
        float4 v = in4[i];
        o2[2*i]   = __floats2half2_rn(v.x, v.y);
        o2[2*i+1] = __floats2half2_rn(v.z, v.w);
    }
}

// transpose+split (vectorized): in [R,C] -> hi/lo fp16 [C,R]  (weights only)
__global__ void split_transpose(const float* __restrict__ in,
                                fp16* __restrict__ hiT, fp16* __restrict__ loT,
                                int R, int C) {
    __shared__ float t[32][33];
    const float* ib = in;
    const int c0 = blockIdx.x * 32, r0 = blockIdx.y * 32;
    const int tid = threadIdx.y * 16 + threadIdx.x;

    #pragma unroll
    for (int it = 0; it < 4; it++) {
        int idx = tid + it * 256;
        int i = idx >> 5, col = idx & 31;
        t[i][col] = ib[(size_t)(r0 + i) * C + c0 + col];
    }
    __syncthreads();

    __half2* h2 = (__half2*)hiT;
    __half2* l2 = (__half2*)loT;
    const int j2 = threadIdx.x;
    #pragma unroll
    for (int it = 0; it < 2; it++) {
        int i = threadIdx.y + it * 16;
        float v0 = t[2*j2][i];
        float v1 = t[2*j2+1][i];
        fp16 h0 = __float2half_rn(v0), h1 = __float2half_rn(v1);
        size_t o2 = (((size_t)(c0 + i) * R + r0) >> 1) + j2;
        h2[o2] = __halves2half2(h0, h1);
        l2[o2] = __floats2half2_rn(v0 - __half2float(h0), v1 - __half2float(h1));
    }
}

// ---------------------------------------------------------------------------
// GEMM core: D(128x128) = A*Bh^T + A*Bl^T, K-major fp16 operands,
// BK=32, 3-stage cp.async pipeline (distance 2), 8 warps (2M x 4N, 64x32 ea).
// ---------------------------------------------------------------------------
__device__ __forceinline__ void gemm_core(
    float (&acc)[4][4][4],
    const fp16* __restrict__ A,
    const fp16* __restrict__ Bh, const fp16* __restrict__ Bl,
    int row0, int col0, int ldA, int ldB, int keff, char* smem)
{
    const int tid = threadIdx.x, wid = tid >> 5, lane = tid & 31;
    const int wm = wid & 1, wn = wid >> 1;
    const uint32_t sbase = smem_u32(smem);
    const int lr = tid >> 2, lc = tid & 3;
    const int nk = keff >> 5;

    #pragma unroll
    for (int i = 0; i < 4; i++)
        #pragma unroll
        for (int j = 0; j < 4; j++)
            #pragma unroll
            for (int q = 0; q < 4; q++) acc[i][j][q] = 0.f;

    #define ISSUE(buf, k0) do {                                               \
        uint32_t so_ = sbase + (buf) * STAGEB;                                \
        _Pragma("unroll")                                                     \
        for (int t_ = 0; t_ < 2; t_++) {                                      \
            int r_ = lr + t_ * 64;                                            \
            uint32_t ro_ = r_ * ROWB + lc * 16;                               \
            const fp16* gA_  = A  + (size_t)(row0 + r_) * ldA + (k0) + lc*8;  \
            const fp16* gBh_ = Bh + (size_t)(col0 + r_) * ldB + (k0) + lc*8;  \
            const fp16* gBl_ = Bl + (size_t)(col0 + r_) * ldB + (k0) + lc*8;  \
            cp16(so_ + ro_,          gA_);                                    \
            cp16(so_ + OFF_BH + ro_, gBh_);                                   \
            cp16(so_ + OFF_BL + ro_, gBl_);                                   \
        }                                                                     \
        cp_commit();                                                          \
    } while (0)

    ISSUE(0, 0);
    if (nk > 1) ISSUE(1, 32);

    for (int kc = 0; kc < nk; kc++) {
        if (kc + 1 < nk) cp_wait1(); else cp_wait0();
        __syncthreads();
        if (kc + 2 < nk) ISSUE((kc + 2) % NSTAGE, (kc + 2) * 32);

        const uint32_t so = sbase + (kc % NSTAGE) * STAGEB;
        #pragma unroll
        for (int kk = 0; kk < 2; kk++) {
            uint32_t ah[4][4], bh[4][2], bl[4][2];
            const uint32_t acoff = kk * 32 + (lane >> 4) * 16;
            #pragma unroll
            for (int mt = 0; mt < 4; mt++) {
                uint32_t ar = (uint32_t)(wm * 64 + mt * 16 + (lane & 15));
                uint32_t aaddr = so + ar * ROWB + acoff;
                LDSM_X4(ah[mt][0], ah[mt][1], ah[mt][2], ah[mt][3], aaddr);
            }
            #pragma unroll
            for (int ntp = 0; ntp < 2; ntp++) {
                uint32_t br = (uint32_t)(wn * 32 + ntp * 16 + (lane & 15));
                uint32_t baddr = so + OFF_BH + br * ROWB + acoff;
                uint32_t t0, t1, t2, t3;
                LDSM_X4(t0, t1, t2, t3, baddr);
                bh[2*ntp][0] = t0; bh[2*ntp][1] = t2;
                bh[2*ntp+1][0] = t1; bh[2*ntp+1][1] = t3;
                LDSM_X4(t0, t1, t2, t3, baddr + (OFF_BL - OFF_BH));
                bl[2*ntp][0] = t0; bl[2*ntp][1] = t2;
                bl[2*ntp+1][0] = t1; bl[2*ntp+1][1] = t3;
            }
            #pragma unroll
            for (int mt = 0; mt < 4; mt++)
                #pragma unroll
                for (int nt = 0; nt < 4; nt++) {
                    MMA16816(acc[mt][nt], ah[mt], bh[nt]);
                    MMA16816(acc[mt][nt], ah[mt], bl[nt]);
                }
        }
    }
    #undef ISSUE
}

// ---------------------------------------------------------------------------
// Epilogue. modes: 0: fp32 = D + bias      1: fp16 = rope(D+bias)
//                  2: fp32 = D * scale     3: fp16 = D
//                  4: fp16 hi/lo = rope(D+bias)
// ---------------------------------------------------------------------------
__device__ __forceinline__ void gemm_epi(
    float (&acc)[4][4][4], int row0, int col0, int b,
    int ldC, unsigned long long cStride,
    const float* __restrict__ bias,
    float* __restrict__ outF, fp16* __restrict__ outHi, fp16* __restrict__ outLo,
    int mode, float scale)
{
    const int tid = threadIdx.x, wid = tid >> 5, lane = tid & 31;
    const int wm = wid & 1, wn = wid >> 1;
    const int g = lane >> 2, tg = lane & 3;
    const float log_theta = 9.210340371976184f;
    #pragma unroll
    for (int mt = 0; mt < 4; mt++) {
        #pragma unroll
        for (int half = 0; half < 2; half++) {
            const int gr = row0 + wm * 64 + mt * 16 + g + half * 8;
            #pragma unroll
            for (int nt = 0; nt < 4; nt++) {
                const int gc = col0 + wn * 32 + nt * 8 + tg * 2;
                float v0 = acc[mt][nt][half * 2];
                float v1 = acc[mt][nt][half * 2 + 1];
                if (mode == 0) {
                    float* o = outF + (size_t)b * cStride + (size_t)gr * ldC + gc;
                    o[0] = v0 + bias[gc];
                    o[1] = v1 + bias[gc + 1];
                } else if (mode == 2) {
                    float* o = outF + (size_t)b * cStride + (size_t)gr * ldC + gc;
                    o[0] = v0 * scale;
                    o[1] = v1 * scale;
                } else {
                    float q0, q1;
                    if (mode == 1 || mode == 4) {
                        float ve = v0 + bias[gc], vo = v1 + bias[gc + 1];
                        float invf = __expf(-((float)gc * (1.0f / CDIM)) * log_theta);
                        float s, co;
                        sincosf((float)(gr & (SEQ - 1)) * invf, &s, &co);
                        q0 = ve * co - vo * s;
                        q1 = vo * co + ve * s;
                    } else { q0 = v0; q1 = v1; }
                    size_t off = (size_t)b * cStride + (size_t)gr * ldC + gc;
                    fp16 h0 = __float2half_rn(q0), h1 = __float2half_rn(q1);
                    *(__half2*)(outHi + off) = __halves2half2(h0, h1);
                    if (mode == 4)
                        *(__half2*)(outLo + off) = __floats2half2_rn(
                            q0 - __half2float(h0), q1 - __half2float(h1));
                }
            }
        }
    }
}

// ---------------------------------------------------------------------------
// Generic GEMM (QK^T, PV, out-proj). causal: 0 none, 1 tile-skip, 2 K-limit.
// causal==2 (PV) also reverses the row mapping: longest tiles launch first.
// ---------------------------------------------------------------------------
__global__ __launch_bounds__(256)
void mma_gemm(const fp16* __restrict__ A,
              const fp16* __restrict__ Bhi, const fp16* __restrict__ Blo,
              int Kdim, int ldA, int ldB, int ldC,
              unsigned long long aStride, unsigned long long bStride,
              unsigned long long cStride,
              const float* __restrict__ bias,
              float* __restrict__ outF,
              fp16* __restrict__ outHi, fp16* __restrict__ outLo,
              int mode, float scale, int causal)
{
    extern __shared__ char smem[];
    int by = blockIdx.y;
    if (causal == 2) by = gridDim.y - 1 - by;      // longest-first for PV
    const int row0 = by * 128, col0 = blockIdx.x * 128, b = blockIdx.z;
    if (causal == 1 && row0 + 127 < col0) return;

    int keff = Kdim;
    if (causal == 2) keff = (row0 + 128 < Kdim) ? row0 + 128 : Kdim;

    float acc[4][4][4];
    gemm_core(acc,
              A + (size_t)b * aStride,
              Bhi + (size_t)b * bStride, Blo + (size_t)b * bStride,
              row0, col0, ldA, ldB, keff, smem);
    gemm_epi(acc, row0, col0, b, ldC, cStride, bias, outF, outHi, outLo,
             mode, scale);
}

// ---------------------------------------------------------------------------
// Merged QKV projection: grid.x = 24; x/8 selects Q, K or V.
// Q: rope+bias -> fp16.  K: rope+bias -> fp16 hi/lo.
// V: bias -> transposed hi/lo fp16 (VT [C,T] per batch) via smem transpose.
// ---------------------------------------------------------------------------
__global__ __launch_bounds__(256)
void qkv_gemm(const fp16* __restrict__ X,
              const fp16* __restrict__ WqH, const fp16* __restrict__ WqL,
              const fp16* __restrict__ WkH, const fp16* __restrict__ WkL,
              const fp16* __restrict__ WvH, const fp16* __restrict__ WvL,
              const float* __restrict__ bq, const float* __restrict__ bk,
              const float* __restrict__ bv,
              fp16* __restrict__ Q,
              fp16* __restrict__ Khi, fp16* __restrict__ Klo,
              fp16* __restrict__ VThi, fp16* __restrict__ VTlo)
{
    extern __shared__ char smem[];
    const int wsel = blockIdx.x >> 3;
    const int col0 = (blockIdx.x & 7) * 128;
    const int row0 = blockIdx.y * 128;

    const fp16 *Bh, *Bl;
    const float* bias;
    if (wsel == 0)      { Bh = WqH; Bl = WqL; bias = bq; }
    else if (wsel == 1) { Bh = WkH; Bl = WkL; bias = bk; }
    else                { Bh = WvH; Bl = WvL; bias = bv; }

    float acc[4][4][4];
    gemm_core(acc, X, Bh, Bl, row0, col0, CDIM, CDIM, CDIM, smem);

    if (wsel < 2) {
        gemm_epi(acc, row0, col0, 0, CDIM, 0ULL, bias, nullptr,
                 wsel == 0 ? Q : Khi, wsel == 0 ? nullptr : Klo,
                 wsel == 0 ? 1 : 4, 1.f);
        return;
    }

    // --- V: transpose 128x128 tile through smem, store VT hi/lo coalesced ---
    const int tid = threadIdx.x, wid = tid >> 5, lane = tid & 31;
    const int wm = wid & 1, wn = wid >> 1;
    const int g = lane >> 2, tg = lane & 3;
    float* ts = (float*)smem;                       // [128 cols][132] layout
    __syncthreads();                                // mainloop done with smem
    #pragma unroll
    for (int mt = 0; mt < 4; mt++) {
        #pragma unroll
        for (int half = 0; half < 2; half++) {
            const int mr = wm * 64 + mt * 16 + g + half * 8;   // m_local
            #pragma unroll
            for (int nt = 0; nt < 4; nt++) {
                const int cc = wn * 32 + nt * 8 + tg * 2;      // c_local
                ts[(cc)     * 132 + mr] = acc[mt][nt][half*2]     + bias[col0 + cc];
                ts[(cc + 1) * 132 + mr] = acc[mt][nt][half*2 + 1] + bias[col0 + cc + 1];
            }
        }
    }
    __syncthreads();

    const int r  = tid >> 1;          // c_local 0..127
    const int hs = tid & 1;           // which 64-wide m half
    const int bv_ = row0 / SEQ;       // batch (tile never straddles batches)
    const int mb  = row0 % SEQ;
    size_t base = (((size_t)bv_ * CDIM + col0 + r) * SEQ + mb + hs * 64) >> 1;
    __half2* oh = (__half2*)VThi + base;
    __half2* ol = (__half2*)VTlo + base;
    const float* row = ts + r * 132 + hs * 64;
    #pragma unroll
    for (int j = 0; j < 32; j++) {
        float2 v = *(const float2*)(row + 2 * j);
        fp16 h0 = __float2half_rn(v.x), h1 = __float2half_rn(v.y);
        oh[j] = __halves2half2(h0, h1);
        ol[j] = __floats2half2_rn(v.x - __half2float(h0), v.y - __half2float(h1));
    }
}

// ---------------------------------------------------------------------------
// Causal softmax: fp32 S -> fp16 P, writes only columns [0, nlim).
// ---------------------------------------------------------------------------
__global__ __launch_bounds__(256)
void softmax_causal(const float* __restrict__ S, fp16* __restrict__ P, int T)
{
    const int t = blockIdx.x, b = blockIdx.y;
    const float* row = S + ((size_t)b * T + t) * T;
    size_t obase = ((size_t)b * T + t) * T;
    const int n = t + 1;
    const int nlim = ((t >> 7) + 1) << 7;   // PV reads s < nlim only
    const int tid = threadIdx.x;

    __shared__ float sm[SEQ];
    __shared__ float red[256];

    float mx = -INFINITY;
    for (int i = tid; i < n; i += 256) {
        float v = row[i];
        sm[i] = v;
        mx = fmaxf(mx, v);
    }
    red[tid] = mx;
    __syncthreads();
    for (int s = 128; s > 0; s >>= 1) {
        if (tid < s) red[tid] = fmaxf(red[tid], red[tid + s]);
        __syncthreads();
    }
    mx = red[0];
    __syncthreads();

    float sum = 0.f;
    for (int i = tid; i < n; i += 256) {
        float e = __expf(sm[i] - mx);
        sm[i] = e;
        sum += e;
    }
    red[tid] = sum;
    __syncthreads();
    for (int s = 128; s > 0; s >>= 1) {
        if (tid < s) red[tid] += red[tid + s];
        __syncthreads();
    }
    float inv = 1.f / red[0];

    for (int i = tid; i < nlim; i += 256) {
        float v = (i < n) ? sm[i] * inv : 0.f;
        P[obase + i] = __float2half_rn(v);
    }
}

// ---------------------------------------------------------------------------
// Launch
// ---------------------------------------------------------------------------
extern "C" void kernel_launch(void* const* d_in, const int* in_sizes, int n_in,
                              void* d_out, int out_size)
{
    const float* x  = (const float*)d_in[0];
    const float* Wq = (const float*)d_in[1];
    const float* bq = (const float*)d_in[2];
    const float* Wk = (const float*)d_in[3];
    const float* bk = (const float*)d_in[4];
    const float* Wv = (const float*)d_in[5];
    const float* bv = (const float*)d_in[6];
    const float* Wo = (const float*)d_in[7];
    const float* bo = (const float*)d_in[8];
    float* out = (float*)d_out;

    const int T = SEQ, C = CDIM;

    float *S;
    fp16 *X, *Q, *Khi, *Klo, *VThi, *VTlo, *P, *O1;
    fp16 *WqThi, *WqTlo, *WkThi, *WkTlo, *WvThi, *WvTlo, *WoThi, *WoTlo;
    cudaGetSymbolAddress((void**)&S, g_S);
    cudaGetSymbolAddress((void**)&X, g_X);
    cudaGetSymbolAddress((void**)&Q, g_Q);
    cudaGetSymbolAddress((void**)&Khi, g_Khi);  cudaGetSymbolAddress((void**)&Klo, g_Klo);
    cudaGetSymbolAddress((void**)&VThi, g_VThi); cudaGetSymbolAddress((void**)&VTlo, g_VTlo);
    cudaGetSymbolAddress((void**)&P, g_P);
    cudaGetSymbolAddress((void**)&O1, g_O1);
    cudaGetSymbolAddress((void**)&WqThi, g_WqThi); cudaGetSymbolAddress((void**)&WqTlo, g_WqTlo);
    cudaGetSymbolAddress((void**)&WkThi, g_WkThi); cudaGetSymbolAddress((void**)&WkTlo, g_WkTlo);
    cudaGetSymbolAddress((void**)&WvThi, g_WvThi); cudaGetSymbolAddress((void**)&WvTlo, g_WvTlo);
    cudaGetSymbolAddress((void**)&WoThi, g_WoThi); cudaGetSymbolAddress((void**)&WoTlo, g_WoTlo);

    cudaFuncSetAttribute(mma_gemm, cudaFuncAttributeMaxDynamicSharedMemorySize, GEMM_SMEM);
    cudaFuncSetAttribute(qkv_gemm, cudaFuncAttributeMaxDynamicSharedMemorySize, GEMM_SMEM);

    // --- conversions ---
    to_half<<<1024, 256>>>(x, X, (size_t)MROWS * C / 4);
    dim3 tT(16, 16);
    split_transpose<<<dim3(C/32, C/32, 1), tT>>>(Wq, WqThi, WqTlo, C, C);
    split_transpose<<<dim3(C/32, C/32, 1), tT>>>(Wk, WkThi, WkTlo, C, C);
    split_transpose<<<dim3(C/32, C/32, 1), tT>>>(Wv, WvThi, WvTlo, C, C);
    split_transpose<<<dim3(C/32, C/32, 1), tT>>>(Wo, WoThi, WoTlo, C, C);

    // --- merged QKV projection (V transposed in-kernel) ---
    dim3 blk(256);
    qkv_gemm<<<dim3(3 * C / 128, MROWS / 128, 1), blk, GEMM_SMEM>>>(
        X, WqThi, WqTlo, WkThi, WkTlo, WvThi, WvTlo,
        bq, bk, bv, Q, Khi, Klo, VThi, VTlo);

    // --- QK^T (causal tile skip): A=Q fp16, B=K hi/lo ---
    dim3 gQK(T/128, T/128, BATCH);
    mma_gemm<<<gQK, blk, GEMM_SMEM>>>(Q, Khi, Klo, C, C, C, T,
        (unsigned long long)T*C, (unsigned long long)T*C, (unsigned long long)T*T,
        nullptr, S, nullptr, nullptr, 2, 0.03125f, 1);

    // --- softmax -> fp16 P ---
    softmax_causal<<<dim3(T, BATCH), 256>>>(S, P, T);

    // --- PV (causal K-limit, longest-first): A=P fp16, B=V^T hi/lo -> O1 fp16
    dim3 gPV(C/128, T/128, BATCH);
    mma_gemm<<<gPV, blk, GEMM_SMEM>>>(P, VThi, VTlo, T, T, T, C,
        (unsigned long long)T*T, (unsigned long long)C*T, (unsigned long long)T*C,
        nullptr, nullptr, O1, nullptr, 3, 1.f, 2);

    // --- output projection: A=O1 fp16, B=Wo^T hi/lo -> fp32 out ---
    dim3 gProj(C/128, MROWS/128, 1);
    mma_gemm<<<gProj, blk, GEMM_SMEM>>>(O1, WoThi, WoTlo, C, C, C, C,
        0ULL, 0ULL, 0ULL, bo, out, nullptr, nullptr, 0, 1.f, 0);
}

// round 13
// speedup vs baseline: 1.0525x; 1.0525x over previous
#include <cuda_runtime.h>
#include <cuda_fp16.h>
#include <math.h>
#include <stdint.h>

// Problem constants (B=4, T=2048, C=1024)
#define BATCH 4
#define SEQ   2048
#define CDIM  1024
#define MROWS (BATCH*SEQ)   // 8192

typedef __half fp16;

// ------------------------- scratch (__device__ globals) ---------------------
__device__ float g_S [(size_t)BATCH*SEQ*SEQ];
__device__ fp16 g_X [MROWS*CDIM];                        // A: single fp16
__device__ fp16 g_Q [MROWS*CDIM];                        // A: single fp16
__device__ fp16 g_Khi[MROWS*CDIM], g_Klo[MROWS*CDIM];    // B: hi/lo
__device__ fp16 g_VThi[MROWS*CDIM], g_VTlo[MROWS*CDIM];  // B: hi/lo, [C,T]/batch
__device__ fp16 g_P [(size_t)BATCH*SEQ*SEQ];             // A: single fp16
__device__ fp16 g_O1[MROWS*CDIM];                        // A: single fp16
__device__ fp16 g_WqThi[CDIM*CDIM], g_WqTlo[CDIM*CDIM];
__device__ fp16 g_WkThi[CDIM*CDIM], g_WkTlo[CDIM*CDIM];
__device__ fp16 g_WvThi[CDIM*CDIM], g_WvTlo[CDIM*CDIM];
__device__ fp16 g_WoThi[CDIM*CDIM], g_WoTlo[CDIM*CDIM];

// ------------------------- PTX helpers (sm_100 base target) -----------------
__device__ __forceinline__ uint32_t smem_u32(const void* p) {
    uint32_t a;
    asm("{ .reg .u64 t; cvta.to.shared.u64 t, %1; cvt.u32.u64 %0, t; }"
        : "=r"(a) : "l"(p));
    return a;
}
__device__ __forceinline__ void cp16(uint32_t s, const void* g) {
    asm volatile("cp.async.cg.shared.global [%0], [%1], 16;"
                 :: "r"(s), "l"(g) : "memory");
}
__device__ __forceinline__ void cp_commit() {
    asm volatile("cp.async.commit_group;" ::: "memory");
}
__device__ __forceinline__ void cp_wait0() {
    asm volatile("cp.async.wait_group 0;" ::: "memory");
}
__device__ __forceinline__ void cp_wait1() {
    asm volatile("cp.async.wait_group 1;" ::: "memory");
}
#define LDSM_X4(r0, r1, r2, r3, a) \
    asm volatile("ldmatrix.sync.aligned.m8n8.x4.shared.b16 {%0,%1,%2,%3}, [%4];" \
                 : "=r"(r0), "=r"(r1), "=r"(r2), "=r"(r3) : "r"(a))
#define MMA16816(c, a, b) \
    asm volatile("mma.sync.aligned.m16n8k16.row.col.f32.f16.f16.f32 " \
                 "{%0,%1,%2,%3}, {%4,%5,%6,%7}, {%8,%9}, {%0,%1,%2,%3};" \
                 : "+f"((c)[0]), "+f"((c)[1]), "+f"((c)[2]), "+f"((c)[3]) \
                 : "r"((a)[0]), "r"((a)[1]), "r"((a)[2]), "r"((a)[3]), \
                   "r"((b)[0]), "r"((b)[1]))

// SMEM tile geometry: 128 rows x 32 fp16, padded to 40 fp16 (80 B) per row.
// Stage = A + Bh + Bl (3 tiles).
#define ROWB 80
#define TILEB (128 * ROWB)           // 10240 B per tile
#define OFF_BH TILEB
#define OFF_BL (2 * TILEB)
#define STAGEB (3 * TILEB)           // 30720 B
#define NSTAGE 3
#define GEMM_SMEM (NSTAGE * STAGEB)  // 92160 B -> 2 CTAs/SM; also >= 128x132 f32

// ---------------------------------------------------------------------------
// Conversion kernels
// ---------------------------------------------------------------------------
__global__ void to_half(const float* __restrict__ in, fp16* __restrict__ out,
                        size_t n4) {
    size_t i = blockIdx.x * (size_t)blockDim.x + threadIdx.x;
    size_t stride = (size_t)gridDim.x * blockDim.x;
    const float4* in4 = (const float4*)in;
    __half2* o2 = (__half2*)out;
    for (; i < n4; i += stride) {
        float4 v = in4[i];
        o2[2*i]   = __floats2half2_rn(v.x, v.y);
        o2[2*i+1] = __floats2half2_rn(v.z, v.w);
    }
}

// transpose+split (vectorized): in [R,C] -> hi/lo fp16 [C,R]  (weights only)
__global__ void split_transpose(const float* __restrict__ in,
                                fp16* __restrict__ hiT, fp16* __restrict__ loT,
                                int R, int C) {
    __shared__ float t[32][33];
    const float* ib = in;
    const int c0 = blockIdx.x * 32, r0 = blockIdx.y * 32;
    const int tid = threadIdx.y * 16 + threadIdx.x;

    #pragma unroll
    for (int it = 0; it < 4; it++) {
        int idx = tid + it * 256;
        int i = idx >> 5, col = idx & 31;
        t[i][col] = ib[(size_t)(r0 + i) * C + c0 + col];
    }
    __syncthreads();

    __half2* h2 = (__half2*)hiT;
    __half2* l2 = (__half2*)loT;
    const int j2 = threadIdx.x;
    #pragma unroll
    for (int it = 0; it < 2; it++) {
        int i = threadIdx.y + it * 16;
        float v0 = t[2*j2][i];
        float v1 = t[2*j2+1][i];
        fp16 h0 = __float2half_rn(v0), h1 = __float2half_rn(v1);
        size_t o2 = (((size_t)(c0 + i) * R + r0) >> 1) + j2;
        h2[o2] = __halves2half2(h0, h1);
        l2[o2] = __floats2half2_rn(v0 - __half2float(h0), v1 - __half2float(h1));
    }
}

// ---------------------------------------------------------------------------
// GEMM core: D(128x128) = A*Bh^T + A*Bl^T, K-major fp16 operands,
// BK=32, 3-stage cp.async pipeline (distance 2), 8 warps (2M x 4N, 64x32 ea).
// ---------------------------------------------------------------------------
__device__ __forceinline__ void gemm_core(
    float (&acc)[4][4][4],
    const fp16* __restrict__ A,
    const fp16* __restrict__ Bh, const fp16* __restrict__ Bl,
    int row0, int col0, int ldA, int ldB, int keff, char* smem)
{
    const int tid = threadIdx.x, wid = tid >> 5, lane = tid & 31;
    const int wm = wid & 1, wn = wid >> 1;
    const uint32_t sbase = smem_u32(smem);
    const int lr = tid >> 2, lc = tid & 3;
    const int nk = keff >> 5;

    #pragma unroll
    for (int i = 0; i < 4; i++)
        #pragma unroll
        for (int j = 0; j < 4; j++)
            #pragma unroll
            for (int q = 0; q < 4; q++) acc[i][j][q] = 0.f;

    #define ISSUE(buf, k0) do {                                               \
        uint32_t so_ = sbase + (buf) * STAGEB;                                \
        _Pragma("unroll")                                                     \
        for (int t_ = 0; t_ < 2; t_++) {                                      \
            int r_ = lr + t_ * 64;                                            \
            uint32_t ro_ = r_ * ROWB + lc * 16;                               \
            const fp16* gA_  = A  + (size_t)(row0 + r_) * ldA + (k0) + lc*8;  \
            const fp16* gBh_ = Bh + (size_t)(col0 + r_) * ldB + (k0) + lc*8;  \
            const fp16* gBl_ = Bl + (size_t)(col0 + r_) * ldB + (k0) + lc*8;  \
            cp16(so_ + ro_,          gA_);                                    \
            cp16(so_ + OFF_BH + ro_, gBh_);                                   \
            cp16(so_ + OFF_BL + ro_, gBl_);                                   \
        }                                                                     \
        cp_commit();                                                          \
    } while (0)

    ISSUE(0, 0);
    if (nk > 1) ISSUE(1, 32);

    for (int kc = 0; kc < nk; kc++) {
        if (kc + 1 < nk) cp_wait1(); else cp_wait0();
        __syncthreads();
        if (kc + 2 < nk) ISSUE((kc + 2) % NSTAGE, (kc + 2) * 32);

        const uint32_t so = sbase + (kc % NSTAGE) * STAGEB;
        #pragma unroll
        for (int kk = 0; kk < 2; kk++) {
            uint32_t ah[4][4], bh[4][2], bl[4][2];
            const uint32_t acoff = kk * 32 + (lane >> 4) * 16;
            #pragma unroll
            for (int mt = 0; mt < 4; mt++) {
                uint32_t ar = (uint32_t)(wm * 64 + mt * 16 + (lane & 15));
                uint32_t aaddr = so + ar * ROWB + acoff;
                LDSM_X4(ah[mt][0], ah[mt][1], ah[mt][2], ah[mt][3], aaddr);
            }
            #pragma unroll
            for (int ntp = 0; ntp < 2; ntp++) {
                uint32_t br = (uint32_t)(wn * 32 + ntp * 16 + (lane & 15));
                uint32_t baddr = so + OFF_BH + br * ROWB + acoff;
                uint32_t t0, t1, t2, t3;
                LDSM_X4(t0, t1, t2, t3, baddr);
                bh[2*ntp][0] = t0; bh[2*ntp][1] = t2;
                bh[2*ntp+1][0] = t1; bh[2*ntp+1][1] = t3;
                LDSM_X4(t0, t1, t2, t3, baddr + (OFF_BL - OFF_BH));
                bl[2*ntp][0] = t0; bl[2*ntp][1] = t2;
                bl[2*ntp+1][0] = t1; bl[2*ntp+1][1] = t3;
            }
            #pragma unroll
            for (int mt = 0; mt < 4; mt++)
                #pragma unroll
                for (int nt = 0; nt < 4; nt++) {
                    MMA16816(acc[mt][nt], ah[mt], bh[nt]);
                    MMA16816(acc[mt][nt], ah[mt], bl[nt]);
                }
        }
    }
    #undef ISSUE
}

// ---------------------------------------------------------------------------
// Epilogue. modes: 0: fp32 = D + bias      1: fp16 = rope(D+bias)
//                  2: fp32 = D * scale     3: fp16 = D
//                  4: fp16 hi/lo = rope(D+bias)
// ---------------------------------------------------------------------------
__device__ __forceinline__ void gemm_epi(
    float (&acc)[4][4][4], int row0, int col0, int b,
    int ldC, unsigned long long cStride,
    const float* __restrict__ bias,
    float* __restrict__ outF, fp16* __restrict__ outHi, fp16* __restrict__ outLo,
    int mode, float scale)
{
    const int tid = threadIdx.x, wid = tid >> 5, lane = tid & 31;
    const int wm = wid & 1, wn = wid >> 1;
    const int g = lane >> 2, tg = lane & 3;
    const float log_theta = 9.210340371976184f;
    #pragma unroll
    for (int mt = 0; mt < 4; mt++) {
        #pragma unroll
        for (int half = 0; half < 2; half++) {
            const int gr = row0 + wm * 64 + mt * 16 + g + half * 8;
            #pragma unroll
            for (int nt = 0; nt < 4; nt++) {
                const int gc = col0 + wn * 32 + nt * 8 + tg * 2;
                float v0 = acc[mt][nt][half * 2];
                float v1 = acc[mt][nt][half * 2 + 1];
                if (mode == 0) {
                    float* o = outF + (size_t)b * cStride + (size_t)gr * ldC + gc;
                    o[0] = v0 + bias[gc];
                    o[1] = v1 + bias[gc + 1];
                } else if (mode == 2) {
                    float* o = outF + (size_t)b * cStride + (size_t)gr * ldC + gc;
                    o[0] = v0 * scale;
                    o[1] = v1 * scale;
                } else {
                    float q0, q1;
                    if (mode == 1 || mode == 4) {
                        float ve = v0 + bias[gc], vo = v1 + bias[gc + 1];
                        float invf = __expf(-((float)gc * (1.0f / CDIM)) * log_theta);
                        float s, co;
                        sincosf((float)(gr & (SEQ - 1)) * invf, &s, &co);
                        q0 = ve * co - vo * s;
                        q1 = vo * co + ve * s;
                    } else { q0 = v0; q1 = v1; }
                    size_t off = (size_t)b * cStride + (size_t)gr * ldC + gc;
                    fp16 h0 = __float2half_rn(q0), h1 = __float2half_rn(q1);
                    *(__half2*)(outHi + off) = __halves2half2(h0, h1);
                    if (mode == 4)
                        *(__half2*)(outLo + off) = __floats2half2_rn(
                            q0 - __half2float(h0), q1 - __half2float(h1));
                }
            }
        }
    }
}

// ---------------------------------------------------------------------------
// Generic GEMM (QK^T, PV, out-proj). causal: 0 none, 1 tile-skip, 2 K-limit.
// causal==2 (PV) also reverses the row mapping: longest tiles launch first.
// ---------------------------------------------------------------------------
__global__ __launch_bounds__(256)
void mma_gemm(const fp16* __restrict__ A,
              const fp16* __restrict__ Bhi, const fp16* __restrict__ Blo,
              int Kdim, int ldA, int ldB, int ldC,
              unsigned long long aStride, unsigned long long bStride,
              unsigned long long cStride,
              const float* __restrict__ bias,
              float* __restrict__ outF,
              fp16* __restrict__ outHi, fp16* __restrict__ outLo,
              int mode, float scale, int causal)
{
    extern __shared__ char smem[];
    int by = blockIdx.y;
    if (causal == 2) by = gridDim.y - 1 - by;      // longest-first for PV
    const int row0 = by * 128, col0 = blockIdx.x * 128, b = blockIdx.z;
    if (causal == 1 && row0 + 127 < col0) return;

    int keff = Kdim;
    if (causal == 2) keff = (row0 + 128 < Kdim) ? row0 + 128 : Kdim;

    float acc[4][4][4];
    gemm_core(acc,
              A + (size_t)b * aStride,
              Bhi + (size_t)b * bStride, Blo + (size_t)b * bStride,
              row0, col0, ldA, ldB, keff, smem);
    gemm_epi(acc, row0, col0, b, ldC, cStride, bias, outF, outHi, outLo,
             mode, scale);
}

// ---------------------------------------------------------------------------
// Merged QKV projection: grid.x = 24; x/8 selects Q, K or V.
// Q: rope+bias -> fp16.  K: rope+bias -> fp16 hi/lo.
// V: bias -> transposed hi/lo fp16 (VT [C,T] per batch) via smem transpose,
//    stores fully warp-coalesced (1 warp per VT row, 128 B per instruction).
// ---------------------------------------------------------------------------
__global__ __launch_bounds__(256)
void qkv_gemm(const fp16* __restrict__ X,
              const fp16* __restrict__ WqH, const fp16* __restrict__ WqL,
              const fp16* __restrict__ WkH, const fp16* __restrict__ WkL,
              const fp16* __restrict__ WvH, const fp16* __restrict__ WvL,
              const float* __restrict__ bq, const float* __restrict__ bk,
              const float* __restrict__ bv,
              fp16* __restrict__ Q,
              fp16* __restrict__ Khi, fp16* __restrict__ Klo,
              fp16* __restrict__ VThi, fp16* __restrict__ VTlo)
{
    extern __shared__ char smem[];
    const int wsel = blockIdx.x >> 3;
    const int col0 = (blockIdx.x & 7) * 128;
    const int row0 = blockIdx.y * 128;

    const fp16 *Bh, *Bl;
    const float* bias;
    if (wsel == 0)      { Bh = WqH; Bl = WqL; bias = bq; }
    else if (wsel == 1) { Bh = WkH; Bl = WkL; bias = bk; }
    else                { Bh = WvH; Bl = WvL; bias = bv; }

    float acc[4][4][4];
    gemm_core(acc, X, Bh, Bl, row0, col0, CDIM, CDIM, CDIM, smem);

    if (wsel < 2) {
        gemm_epi(acc, row0, col0, 0, CDIM, 0ULL, bias, nullptr,
                 wsel == 0 ? Q : Khi, wsel == 0 ? nullptr : Klo,
                 wsel == 0 ? 1 : 4, 1.f);
        return;
    }

    // --- V: transpose 128x128 tile through smem, store VT hi/lo coalesced ---
    const int tid = threadIdx.x, wid = tid >> 5, lane = tid & 31;
    const int wm = wid & 1, wn = wid >> 1;
    const int g = lane >> 2, tg = lane & 3;
    float* ts = (float*)smem;                       // [128 c][132 m] layout
    __syncthreads();                                // mainloop done with smem
    #pragma unroll
    for (int mt = 0; mt < 4; mt++) {
        #pragma unroll
        for (int half = 0; half < 2; half++) {
            const int mr = wm * 64 + mt * 16 + g + half * 8;   // m_local
            #pragma unroll
            for (int nt = 0; nt < 4; nt++) {
                const int cc = wn * 32 + nt * 8 + tg * 2;      // c_local
                ts[(cc)     * 132 + mr] = acc[mt][nt][half*2]     + bias[col0 + cc];
                ts[(cc + 1) * 132 + mr] = acc[mt][nt][half*2 + 1] + bias[col0 + cc + 1];
            }
        }
    }
    __syncthreads();

    // One warp per VT row: each store instruction = 32 consecutive half2
    // (128 B contiguous). 16 passes x 8 warps cover all 128 rows.
    const int bv_ = row0 / SEQ;       // batch (tile never straddles batches)
    const int mb  = row0 % SEQ;
    __half2* oh = (__half2*)VThi;
    __half2* ol = (__half2*)VTlo;
    #pragma unroll
    for (int pass = 0; pass < 16; pass++) {
        const int r = pass * 8 + wid;                          // c_local
        const size_t base2 = (((size_t)bv_ * CDIM + col0 + r) * SEQ + mb) >> 1;
        const float* rowp = ts + r * 132;
        #pragma unroll
        for (int it = 0; it < 2; it++) {
            float2 v = *(const float2*)(rowp + it * 64 + 2 * lane);
            fp16 h0 = __float2half_rn(v.x), h1 = __float2half_rn(v.y);
            oh[base2 + it * 32 + lane] = __halves2half2(h0, h1);
            ol[base2 + it * 32 + lane] = __floats2half2_rn(
                v.x - __half2float(h0), v.y - __half2float(h1));
        }
    }
}

// ---------------------------------------------------------------------------
// Causal softmax: fp32 S -> fp16 P, writes only columns [0, nlim).
// ---------------------------------------------------------------------------
__global__ __launch_bounds__(256)
void softmax_causal(const float* __restrict__ S, fp16* __restrict__ P, int T)
{
    const int t = blockIdx.x, b = blockIdx.y;
    const float* row = S + ((size_t)b * T + t) * T;
    size_t obase = ((size_t)b * T + t) * T;
    const int n = t + 1;
    const int nlim = ((t >> 7) + 1) << 7;   // PV reads s < nlim only
    const int tid = threadIdx.x;

    __shared__ float sm[SEQ];
    __shared__ float red[256];

    float mx = -INFINITY;
    for (int i = tid; i < n; i += 256) {
        float v = row[i];
        sm[i] = v;
        mx = fmaxf(mx, v);
    }
    red[tid] = mx;
    __syncthreads();
    for (int s = 128; s > 0; s >>= 1) {
        if (tid < s) red[tid] = fmaxf(red[tid], red[tid + s]);
        __syncthreads();
    }
    mx = red[0];
    __syncthreads();

    float sum = 0.f;
    for (int i = tid; i < n; i += 256) {
        float e = __expf(sm[i] - mx);
        sm[i] = e;
        sum += e;
    }
    red[tid] = sum;
    __syncthreads();
    for (int s = 128; s > 0; s >>= 1) {
        if (tid < s) red[tid] += red[tid + s];
        __syncthreads();
    }
    float inv = 1.f / red[0];

    for (int i = tid; i < nlim; i += 256) {
        float v = (i < n) ? sm[i] * inv : 0.f;
        P[obase + i] = __float2half_rn(v);
    }
}

// ---------------------------------------------------------------------------
// Launch
// ---------------------------------------------------------------------------
extern "C" void kernel_launch(void* const* d_in, const int* in_sizes, int n_in,
                              void* d_out, int out_size)
{
    const float* x  = (const float*)d_in[0];
    const float* Wq = (const float*)d_in[1];
    const float* bq = (const float*)d_in[2];
    const float* Wk = (const float*)d_in[3];
    const float* bk = (const float*)d_in[4];
    const float* Wv = (const float*)d_in[5];
    const float* bv = (const float*)d_in[6];
    const float* Wo = (const float*)d_in[7];
    const float* bo = (const float*)d_in[8];
    float* out = (float*)d_out;

    const int T = SEQ, C = CDIM;

    float *S;
    fp16 *X, *Q, *Khi, *Klo, *VThi, *VTlo, *P, *O1;
    fp16 *WqThi, *WqTlo, *WkThi, *WkTlo, *WvThi, *WvTlo, *WoThi, *WoTlo;
    cudaGetSymbolAddress((void**)&S, g_S);
    cudaGetSymbolAddress((void**)&X, g_X);
    cudaGetSymbolAddress((void**)&Q, g_Q);
    cudaGetSymbolAddress((void**)&Khi, g_Khi);  cudaGetSymbolAddress((void**)&Klo, g_Klo);
    cudaGetSymbolAddress((void**)&VThi, g_VThi); cudaGetSymbolAddress((void**)&VTlo, g_VTlo);
    cudaGetSymbolAddress((void**)&P, g_P);
    cudaGetSymbolAddress((void**)&O1, g_O1);
    cudaGetSymbolAddress((void**)&WqThi, g_WqThi); cudaGetSymbolAddress((void**)&WqTlo, g_WqTlo);
    cudaGetSymbolAddress((void**)&WkThi, g_WkThi); cudaGetSymbolAddress((void**)&WkTlo, g_WkTlo);
    cudaGetSymbolAddress((void**)&WvThi, g_WvThi); cudaGetSymbolAddress((void**)&WvTlo, g_WvTlo);
    cudaGetSymbolAddress((void**)&WoThi, g_WoThi); cudaGetSymbolAddress((void**)&WoTlo, g_WoTlo);

    cudaFuncSetAttribute(mma_gemm, cudaFuncAttributeMaxDynamicSharedMemorySize, GEMM_SMEM);
    cudaFuncSetAttribute(qkv_gemm, cudaFuncAttributeMaxDynamicSharedMemorySize, GEMM_SMEM);

    // --- conversions ---
    to_half<<<1024, 256>>>(x, X, (size_t)MROWS * C / 4);
    dim3 tT(16, 16);
    split_transpose<<<dim3(C/32, C/32, 1), tT>>>(Wq, WqThi, WqTlo, C, C);
    split_transpose<<<dim3(C/32, C/32, 1), tT>>>(Wk, WkThi, WkTlo, C, C);
    split_transpose<<<dim3(C/32, C/32, 1), tT>>>(Wv, WvThi, WvTlo, C, C);
    split_transpose<<<dim3(C/32, C/32, 1), tT>>>(Wo, WoThi, WoTlo, C, C);

    // --- merged QKV projection (V transposed in-kernel) ---
    dim3 blk(256);
    qkv_gemm<<<dim3(3 * C / 128, MROWS / 128, 1), blk, GEMM_SMEM>>>(
        X, WqThi, WqTlo, WkThi, WkTlo, WvThi, WvTlo,
        bq, bk, bv, Q, Khi, Klo, VThi, VTlo);

    // --- QK^T (causal tile skip): A=Q fp16, B=K hi/lo ---
    dim3 gQK(T/128, T/128, BATCH);
    mma_gemm<<<gQK, blk, GEMM_SMEM>>>(Q, Khi, Klo, C, C, C, T,
        (unsigned long long)T*C, (unsigned long long)T*C, (unsigned long long)T*T,
        nullptr, S, nullptr, nullptr, 2, 0.03125f, 1);

    // --- softmax -> fp16 P ---
    softmax_causal<<<dim3(T, BATCH), 256>>>(S, P, T);

    // --- PV (causal K-limit, longest-first): A=P fp16, B=V^T hi/lo -> O1 fp16
    dim3 gPV(C/128, T/128, BATCH);
    mma_gemm<<<gPV, blk, GEMM_SMEM>>>(P, VThi, VTlo, T, T, T, C,
        (unsigned long long)T*T, (unsigned long long)C*T, (unsigned long long)T*C,
        nullptr, nullptr, O1, nullptr, 3, 1.f, 2);

    // --- output projection: A=O1 fp16, B=Wo^T hi/lo -> fp32 out ---
    dim3 gProj(C/128, MROWS/128, 1);
    mma_gemm<<<gProj, blk, GEMM_SMEM>>>(O1, WoThi, WoTlo, C, C, C, C,
        0ULL, 0ULL, 0ULL, bo, out, nullptr, nullptr, 0, 1.f, 0);
}